// round 12
// baseline (speedup 1.0000x reference)
#include <cuda_runtime.h>

// BallPredictorGNN — sparse dependency cone + linear-GAT factorization.
// 3 kernels: pass1(+was/wad prep) -> pass2 -> agg1(+final via done-counter).
// Scans batch 4 independent int4 loads per thread (MLP=4) for latency hiding.
// State reset by the final block each call; static zero-init covers call #1.

#define NMAX      20480
#define FIN       128
#define H1C       256
#define C2        64
#define SRCA_CAP  1024
#define EB_CAP    65536
#define LIST_CAP  4096
#define DEG_CAP   512
#define AGG_GRID  64
#define SCAN_BLK  157          // ceil(160000 quads / (256*4))

__device__ int   g_need1[NMAX];
__device__ int   g_cntA, g_cntB, g_cnt1, g_done;
__device__ int   g_srcA[SRCA_CAP];
__device__ int   g_srcB[EB_CAP];
__device__ int   g_dstB[EB_CAP];
__device__ int   g_list1[LIST_CAP];
__device__ float g_was[FIN * 4];         // [f*4+h]
__device__ float g_wad[FIN * 4];
__device__ float g_g2[(size_t)NMAX * C2];
__device__ float g_as2[NMAX], g_ad2[NMAX];

__device__ __forceinline__ void mark_need1(int v) {
    if (atomicExch(&g_need1[v], 1) == 0) {
        int p = atomicAdd(&g_cnt1, 1);
        if (p < LIST_CAP) g_list1[p] = v;
    }
}

__device__ __forceinline__ void p1_hit(const int* ei, int E, int N, int base, int k) {
    int src = ei[base + k];
    if ((unsigned)src >= (unsigned)N) return;
    int p = atomicAdd(&g_cntA, 1);
    if (p < SRCA_CAP) g_srcA[p] = src;
    mark_need1(src);
}

// blocks 0-7: was/wad prep; blocks 8+: scan dst column for edges into ball
__global__ void k_pass1(const int* __restrict__ ei, int E, int ball, int N,
                        const float* __restrict__ W1,
                        const float* __restrict__ a_src1, const float* __restrict__ a_dst1) {
    const int b = blockIdx.x, t = threadIdx.x;
    const int w = t >> 5, l = t & 31;
    if (b == 0 && t == 0) mark_need1(ball);
    if (b < 8) {
        __shared__ float s_red[16];
        int h = t >> 6, c = t & 63;
        float as = a_src1[h * 64 + c], ad = a_dst1[h * 64 + c];
        for (int f = b * 16; f < b * 16 + 16; f++) {
            float wv = W1[f * H1C + t];
            float ps = wv * as, pd = wv * ad;
#pragma unroll
            for (int o = 16; o; o >>= 1) {
                ps += __shfl_down_sync(~0u, ps, o);
                pd += __shfl_down_sync(~0u, pd, o);
            }
            if (l == 0) { s_red[w] = ps; s_red[8 + w] = pd; }
            __syncthreads();
            if (t < 4) {
                g_was[f * 4 + t] = s_red[2 * t] + s_red[2 * t + 1];
                g_wad[f * 4 + t] = s_red[8 + 2 * t] + s_red[8 + 2 * t + 1];
            }
            __syncthreads();
        }
        return;
    }
    const int nq = (E + 3) >> 2;
    const int* dcol = ei + E;
    const int S = (gridDim.x - 8) * 256;
    int q = (b - 8) * 256 + t;
    // main: 4 independent int4 loads in flight per thread
    for (; q + 3 * S < nq; q += 4 * S) {
        int4 v0 = *reinterpret_cast<const int4*>(dcol + 4 * q);
        int4 v1 = *reinterpret_cast<const int4*>(dcol + 4 * (q + S));
        int4 v2 = *reinterpret_cast<const int4*>(dcol + 4 * (q + 2 * S));
        int4 v3 = *reinterpret_cast<const int4*>(dcol + 4 * (q + 3 * S));
        if (v0.x == ball) p1_hit(ei, E, N, 4 * q, 0);
        if (v0.y == ball) p1_hit(ei, E, N, 4 * q, 1);
        if (v0.z == ball) p1_hit(ei, E, N, 4 * q, 2);
        if (v0.w == ball) p1_hit(ei, E, N, 4 * q, 3);
        if (v1.x == ball) p1_hit(ei, E, N, 4 * (q + S), 0);
        if (v1.y == ball) p1_hit(ei, E, N, 4 * (q + S), 1);
        if (v1.z == ball) p1_hit(ei, E, N, 4 * (q + S), 2);
        if (v1.w == ball) p1_hit(ei, E, N, 4 * (q + S), 3);
        if (v2.x == ball) p1_hit(ei, E, N, 4 * (q + 2 * S), 0);
        if (v2.y == ball) p1_hit(ei, E, N, 4 * (q + 2 * S), 1);
        if (v2.z == ball) p1_hit(ei, E, N, 4 * (q + 2 * S), 2);
        if (v2.w == ball) p1_hit(ei, E, N, 4 * (q + 2 * S), 3);
        if (v3.x == ball) p1_hit(ei, E, N, 4 * (q + 3 * S), 0);
        if (v3.y == ball) p1_hit(ei, E, N, 4 * (q + 3 * S), 1);
        if (v3.z == ball) p1_hit(ei, E, N, 4 * (q + 3 * S), 2);
        if (v3.w == ball) p1_hit(ei, E, N, 4 * (q + 3 * S), 3);
    }
    for (; q < nq; q += S) {
        int base = q * 4;
        int d[4];
        if (base + 4 <= E) {
            int4 v = *reinterpret_cast<const int4*>(dcol + base);
            d[0] = v.x; d[1] = v.y; d[2] = v.z; d[3] = v.w;
        } else {
            for (int k = 0; k < 4; k++) d[k] = (base + k < E) ? dcol[base + k] : -1;
        }
#pragma unroll
        for (int k = 0; k < 4; k++) if (d[k] == ball) p1_hit(ei, E, N, base, k);
    }
}

__device__ __forceinline__ void p2_hit(const int* ei, int N, int base, int k, int dst) {
    if ((unsigned)dst >= (unsigned)N) return;
    if (g_need1[dst]) {
        int src = ei[base + k];
        if ((unsigned)src >= (unsigned)N) return;
        int p = atomicAdd(&g_cntB, 1);
        if (p < EB_CAP) { g_srcB[p] = src; g_dstB[p] = dst; }
    }
}

__global__ void k_pass2(const int* __restrict__ ei, int E, int N) {
    const int nq = (E + 3) >> 2;
    const int* dcol = ei + E;
    const int S = gridDim.x * 256;
    int q = blockIdx.x * 256 + threadIdx.x;
    for (; q + 3 * S < nq; q += 4 * S) {
        int4 v0 = *reinterpret_cast<const int4*>(dcol + 4 * q);
        int4 v1 = *reinterpret_cast<const int4*>(dcol + 4 * (q + S));
        int4 v2 = *reinterpret_cast<const int4*>(dcol + 4 * (q + 2 * S));
        int4 v3 = *reinterpret_cast<const int4*>(dcol + 4 * (q + 3 * S));
        p2_hit(ei, N, 4 * q, 0, v0.x);  p2_hit(ei, N, 4 * q, 1, v0.y);
        p2_hit(ei, N, 4 * q, 2, v0.z);  p2_hit(ei, N, 4 * q, 3, v0.w);
        p2_hit(ei, N, 4 * (q + S), 0, v1.x);  p2_hit(ei, N, 4 * (q + S), 1, v1.y);
        p2_hit(ei, N, 4 * (q + S), 2, v1.z);  p2_hit(ei, N, 4 * (q + S), 3, v1.w);
        p2_hit(ei, N, 4 * (q + 2 * S), 0, v2.x);  p2_hit(ei, N, 4 * (q + 2 * S), 1, v2.y);
        p2_hit(ei, N, 4 * (q + 2 * S), 2, v2.z);  p2_hit(ei, N, 4 * (q + 2 * S), 3, v2.w);
        p2_hit(ei, N, 4 * (q + 3 * S), 0, v3.x);  p2_hit(ei, N, 4 * (q + 3 * S), 1, v3.y);
        p2_hit(ei, N, 4 * (q + 3 * S), 2, v3.z);  p2_hit(ei, N, 4 * (q + 3 * S), 3, v3.w);
    }
    for (; q < nq; q += S) {
        int base = q * 4;
        int d[4];
        if (base + 4 <= E) {
            int4 v = *reinterpret_cast<const int4*>(dcol + base);
            d[0] = v.x; d[1] = v.y; d[2] = v.z; d[3] = v.w;
        } else {
            for (int k = 0; k < 4; k++) d[k] = (base + k < E) ? dcol[base + k] : -1;
        }
#pragma unroll
        for (int k = 0; k < 4; k++) p2_hit(ei, N, base, k, d[k]);
    }
}

// One block per need1 node; LAST finishing block also runs the final phase.
__global__ void k_agg1(const float* __restrict__ x, const float* __restrict__ W1,
                       const float* __restrict__ b1, const float* __restrict__ W2,
                       const float* __restrict__ a_src2, const float* __restrict__ a_dst2,
                       const float* __restrict__ b2,
                       const float* __restrict__ fc1_w, const float* __restrict__ fc1_b,
                       const float* __restrict__ fc2_w, const float* __restrict__ fc2_b,
                       float* __restrict__ out, int ball) {
    __shared__ float s_was[FIN * 4];
    __shared__ float s_wad[FIN * 4];
    __shared__ int   s_src[DEG_CAP];
    __shared__ float s_e[DEG_CAP * 4];
    __shared__ float s_xv[FIN];
    __shared__ float s_xagg[4 * FIN];
    __shared__ float s_r1[H1C];
    __shared__ float s_part[4 * C2];
    __shared__ float s_g2[C2];
    __shared__ float s_adv[4];
    __shared__ float s_inv[4];
    __shared__ int   s_cnt;
    __shared__ float s_fc1[C2 * 32];
    __shared__ int   s_idx[SRCA_CAP + 1];
    __shared__ float sw[SRCA_CAP + 1];
    __shared__ float s_o[C2];
    __shared__ float s_p2[8 * 32];
    __shared__ float s_z[32];
    __shared__ float s_red[16];
    __shared__ int   s_last;
    const int t = threadIdx.x, w = t >> 5, l = t & 31, b = blockIdx.x;
    const int n1 = min(g_cnt1, LIST_CAP);
    const int cb = min(g_cntB, EB_CAP);

    for (int i = t; i < C2 * 32; i += 256) s_fc1[i] = fc1_w[i];

    if (b < n1) {
        for (int i = t; i < FIN * 4; i += 256) { s_was[i] = g_was[i]; s_wad[i] = g_wad[i]; }
        for (int it = b; it < n1; it += AGG_GRID) {
            int v = g_list1[it];
            if (t == 0) s_cnt = 0;
            if (t < FIN) s_xv[t] = x[(size_t)v * FIN + t];
            __syncthreads();
            for (int j = t; j < cb; j += 256) {
                if (g_dstB[j] == v) {
                    int p = atomicAdd(&s_cnt, 1);
                    if (p < DEG_CAP - 1) s_src[p] = g_srcB[j];
                }
            }
            __syncthreads();
            if (t == 0) {
                int p = min(s_cnt, DEG_CAP - 1);
                s_src[p] = v;                 // appended self-loop
                s_cnt = p + 1;
            }
            if (w < 4) {                      // dst logits: x[v] . wad[:,h]
                float p = 0.f;
                for (int f = l; f < FIN; f += 32) p += s_xv[f] * s_wad[f * 4 + w];
#pragma unroll
                for (int o = 16; o; o >>= 1) p += __shfl_down_sync(~0u, p, o);
                if (l == 0) s_adv[w] = p;
            }
            __syncthreads();
            const int n = s_cnt;
            for (int j = w; j < n; j += 8) {  // src logits, warp per edge
                const float4 xv4 = reinterpret_cast<const float4*>(
                                       x + (size_t)s_src[j] * FIN)[l];
                float ph0 = 0.f, ph1 = 0.f, ph2 = 0.f, ph3 = 0.f;
                const float xs[4] = {xv4.x, xv4.y, xv4.z, xv4.w};
#pragma unroll
                for (int k = 0; k < 4; k++) {
                    int f = 4 * l + k;
                    ph0 += xs[k] * s_was[f * 4 + 0];
                    ph1 += xs[k] * s_was[f * 4 + 1];
                    ph2 += xs[k] * s_was[f * 4 + 2];
                    ph3 += xs[k] * s_was[f * 4 + 3];
                }
#pragma unroll
                for (int o = 16; o; o >>= 1) {
                    ph0 += __shfl_down_sync(~0u, ph0, o);
                    ph1 += __shfl_down_sync(~0u, ph1, o);
                    ph2 += __shfl_down_sync(~0u, ph2, o);
                    ph3 += __shfl_down_sync(~0u, ph3, o);
                }
                if (l == 0) {
                    float e0 = ph0 + s_adv[0], e1 = ph1 + s_adv[1];
                    float e2 = ph2 + s_adv[2], e3 = ph3 + s_adv[3];
                    s_e[j * 4 + 0] = (e0 > 0.f) ? e0 : 0.2f * e0;  // leaky_relu
                    s_e[j * 4 + 1] = (e1 > 0.f) ? e1 : 0.2f * e1;
                    s_e[j * 4 + 2] = (e2 > 0.f) ? e2 : 0.2f * e2;
                    s_e[j * 4 + 3] = (e3 > 0.f) ? e3 : 0.2f * e3;
                }
            }
            __syncthreads();
            if (t < 4) {                      // stable softmax per head
                float m = -1e30f;
                for (int j = 0; j < n; j++) m = fmaxf(m, s_e[j * 4 + t]);
                float s = 0.f;
                for (int j = 0; j < n; j++) {
                    float ww = expf(s_e[j * 4 + t] - m);
                    s_e[j * 4 + t] = ww; s += ww;
                }
                s_inv[t] = 1.f / (s + 1e-16f);
            }
            __syncthreads();
            if (t < FIN) {                    // xagg, 4-way unrolled gather
                float a0 = 0.f, a1 = 0.f, a2 = 0.f, a3 = 0.f;
                int j = 0;
                for (; j + 4 <= n; j += 4) {
                    float x0 = x[(size_t)s_src[j + 0] * FIN + t];
                    float x1 = x[(size_t)s_src[j + 1] * FIN + t];
                    float x2 = x[(size_t)s_src[j + 2] * FIN + t];
                    float x3 = x[(size_t)s_src[j + 3] * FIN + t];
                    a0 += s_e[(j+0)*4+0]*x0 + s_e[(j+1)*4+0]*x1 + s_e[(j+2)*4+0]*x2 + s_e[(j+3)*4+0]*x3;
                    a1 += s_e[(j+0)*4+1]*x0 + s_e[(j+1)*4+1]*x1 + s_e[(j+2)*4+1]*x2 + s_e[(j+3)*4+1]*x3;
                    a2 += s_e[(j+0)*4+2]*x0 + s_e[(j+1)*4+2]*x1 + s_e[(j+2)*4+2]*x2 + s_e[(j+3)*4+2]*x3;
                    a3 += s_e[(j+0)*4+3]*x0 + s_e[(j+1)*4+3]*x1 + s_e[(j+2)*4+3]*x2 + s_e[(j+3)*4+3]*x3;
                }
                for (; j < n; j++) {
                    float xv = x[(size_t)s_src[j] * FIN + t];
                    a0 += s_e[j*4+0]*xv; a1 += s_e[j*4+1]*xv;
                    a2 += s_e[j*4+2]*xv; a3 += s_e[j*4+3]*xv;
                }
                s_xagg[0 * FIN + t] = a0 * s_inv[0];
                s_xagg[1 * FIN + t] = a1 * s_inv[1];
                s_xagg[2 * FIN + t] = a2 * s_inv[2];
                s_xagg[3 * FIN + t] = a3 * s_inv[3];
            }
            __syncthreads();
            {                                 // @W1 -> r1
                const int h = t >> 6;
                float acc = 0.f;
#pragma unroll 8
                for (int f = 0; f < FIN; f++)
                    acc += s_xagg[h * FIN + f] * W1[f * H1C + t];
                s_r1[t] = fmaxf(acc + b1[t], 0.f);
            }
            __syncthreads();
            {                                 // g2 = r1 @ W2
                const int c = t & 63, q = t >> 6;
                float p = 0.f;
#pragma unroll 16
                for (int k = q * 64; k < q * 64 + 64; k++)
                    p += s_r1[k] * W2[k * C2 + c];
                s_part[q * C2 + c] = p;
            }
            __syncthreads();
            if (t < C2) {
                float g = s_part[t] + s_part[C2 + t] + s_part[2 * C2 + t] + s_part[3 * C2 + t];
                s_g2[t] = g;
                g_g2[(size_t)v * C2 + t] = g;
            }
            __syncthreads();
            if (w < 2) {                      // layer-2 logits: g2 . a_{src,dst}2
                const float* av = w ? a_dst2 : a_src2;
                float p = s_g2[l] * av[l] + s_g2[l + 32] * av[l + 32];
#pragma unroll
                for (int o = 16; o; o >>= 1) p += __shfl_down_sync(~0u, p, o);
                if (l == 0) { if (w) g_ad2[v] = p; else g_as2[v] = p; }
            }
            __syncthreads();
        }
    }

    // ---- done counter: last-finishing block runs the final phase ----
    __syncthreads();
    if (t == 0) {
        __threadfence();
        s_last = (atomicAdd(&g_done, 1) + 1 == gridDim.x) ? 1 : 0;
        if (s_last) __threadfence();
    }
    __syncthreads();
    if (!s_last) return;

    // ================= final (one block) ==================================
    const int nA = min(g_cntA, SRCA_CAP);
    const int cnt = nA + 1;
    for (int j = t; j < cnt; j += 256) s_idx[j] = (j < nA) ? g_srcA[j] : ball;
    __syncthreads();
    const float adv = g_ad2[ball];
    for (int j = t; j < cnt; j += 256) {
        float e = g_as2[s_idx[j]] + adv;
        sw[j] = (e > 0.f) ? e : 0.2f * e;
    }
    __syncthreads();
    float lm = -1e30f;
    for (int j = t; j < cnt; j += 256) lm = fmaxf(lm, sw[j]);
#pragma unroll
    for (int o = 16; o; o >>= 1) lm = fmaxf(lm, __shfl_down_sync(~0u, lm, o));
    if (l == 0) s_red[w] = lm;
    __syncthreads();
    if (t < 8) {
        float v = s_red[t];
#pragma unroll
        for (int o = 4; o; o >>= 1) v = fmaxf(v, __shfl_down_sync(0xffu, v, o));
        if (t == 0) s_red[0] = v;
    }
    __syncthreads();
    const float m = s_red[0];
    float ls = 0.f;
    for (int j = t; j < cnt; j += 256) { float ww = expf(sw[j] - m); sw[j] = ww; ls += ww; }
#pragma unroll
    for (int o = 16; o; o >>= 1) ls += __shfl_down_sync(~0u, ls, o);
    if (l == 0) s_red[8 + w] = ls;
    __syncthreads();
    if (t < 8) {
        float v = s_red[8 + t];
#pragma unroll
        for (int o = 4; o; o >>= 1) v += __shfl_down_sync(0xffu, v, o);
        if (t == 0) s_red[8] = v;
    }
    __syncthreads();
    const float sinv = 1.f / (s_red[8] + 1e-16f);
    {   // aggregate g2: 4 j-chunks x 64 cols (rows L2-hot)
        const int c = t & 63, q = t >> 6;
        float acc = 0.f;
        for (int j = q; j < cnt; j += 4)
            acc += sw[j] * g_g2[(size_t)s_idx[j] * C2 + c];
        s_part[q * C2 + c] = acc;
    }
    __syncthreads();
    if (t < C2) {
        float o = (s_part[t] + s_part[C2 + t] + s_part[2 * C2 + t] + s_part[3 * C2 + t])
                  * sinv + b2[t];
        s_o[t] = fmaxf(o, 0.f);
    }
    __syncthreads();
    {   // fc1 (weights in smem): 8 k-chunks x 32 outputs
        const int o = t & 31, q = t >> 5;
        float p = 0.f;
#pragma unroll
        for (int k = q * 8; k < q * 8 + 8; k++) p += s_o[k] * s_fc1[k * 32 + o];
        s_p2[q * 32 + o] = p;
    }
    __syncthreads();
    if (t < 32) {
        float a = fc1_b[t];
#pragma unroll
        for (int q = 0; q < 8; q++) a += s_p2[q * 32 + t];
        s_z[t] = fmaxf(a, 0.f);
    }
    __syncthreads();
    if (t < 2) {
        float a = fc2_b[t];
        for (int k = 0; k < 32; k++) a += s_z[k] * fc2_w[k * 2 + t];
        out[t] = a;
    }
    // ---- reset state for next graph replay ----
    __syncthreads();
    const int n1r = min(g_cnt1, LIST_CAP);
    for (int i = t; i < n1r; i += 256) g_need1[g_list1[i]] = 0;
    if (t == 0) { g_cntA = 0; g_cntB = 0; g_cnt1 = 0; g_done = 0; }
}

extern "C" void kernel_launch(void* const* d_in, const int* in_sizes, int n_in,
                              void* d_out, int out_size) {
    const float* x      = (const float*)d_in[0];
    const int*   ei     = (const int*)d_in[1];   // int32 (JAX x64-disabled)
    const float* W1     = (const float*)d_in[2];
    const float* a_src1 = (const float*)d_in[3];
    const float* a_dst1 = (const float*)d_in[4];
    const float* b1     = (const float*)d_in[5];
    const float* W2     = (const float*)d_in[6];
    const float* a_src2 = (const float*)d_in[7];
    const float* a_dst2 = (const float*)d_in[8];
    const float* b2     = (const float*)d_in[9];
    const float* fc1_w  = (const float*)d_in[10];
    const float* fc1_b  = (const float*)d_in[11];
    const float* fc2_w  = (const float*)d_in[12];
    const float* fc2_b  = (const float*)d_in[13];

    int N = in_sizes[0] / FIN;   // 20000
    int E = in_sizes[1] / 2;     // 640000
    int ball = N - 1;

    k_pass1<<<8 + SCAN_BLK, 256>>>(ei, E, ball, N, W1, a_src1, a_dst1);
    k_pass2<<<SCAN_BLK, 256>>>(ei, E, N);
    k_agg1 <<<AGG_GRID, 256>>>(x, W1, b1, W2, a_src2, a_dst2,
                               b2, fc1_w, fc1_b, fc2_w, fc2_b,
                               (float*)d_out, ball);
}

// round 13
// speedup vs baseline: 1.1441x; 1.1441x over previous
#include <cuda_runtime.h>

// BallPredictorGNN — sparse dependency cone + linear-GAT factorization.
// 3 kernels: pass1(+was/wad prep) -> pass2 -> agg1(+final via done-counter).
// R13: prep loads all 16 W1 rows up-front + interleaved reductions (the
// serial 16-round prep was the hidden 10us critical path of k_pass1).

#define NMAX      20480
#define FIN       128
#define H1C       256
#define C2        64
#define SRCA_CAP  1024
#define EB_CAP    65536
#define LIST_CAP  4096
#define DEG_CAP   512
#define AGG_GRID  64
#define SCAN_BLK  157

__device__ int   g_need1[NMAX];
__device__ int   g_cntA, g_cntB, g_cnt1, g_done;
__device__ int   g_srcA[SRCA_CAP];
__device__ int   g_srcB[EB_CAP];
__device__ int   g_dstB[EB_CAP];
__device__ int   g_list1[LIST_CAP];
__device__ float g_was[FIN * 4];         // [f*4+h]
__device__ float g_wad[FIN * 4];
__device__ float g_g2[(size_t)NMAX * C2];
__device__ float g_as2[NMAX], g_ad2[NMAX];

__device__ __forceinline__ void mark_need1(int v) {
    if (atomicExch(&g_need1[v], 1) == 0) {
        int p = atomicAdd(&g_cnt1, 1);
        if (p < LIST_CAP) g_list1[p] = v;
    }
}

__device__ __forceinline__ void p1_hit(const int* ei, int E, int N, int base, int k) {
    int src = ei[base + k];
    if ((unsigned)src >= (unsigned)N) return;
    int p = atomicAdd(&g_cntA, 1);
    if (p < SRCA_CAP) g_srcA[p] = src;
    mark_need1(src);
}

// blocks 0-7: was/wad prep (latency-flat); blocks 8+: scan dst column for ball
__global__ void k_pass1(const int* __restrict__ ei, int E, int ball, int N,
                        const float* __restrict__ W1,
                        const float* __restrict__ a_src1, const float* __restrict__ a_dst1) {
    const int b = blockIdx.x, t = threadIdx.x;
    const int w = t >> 5, l = t & 31;
    if (b == 0 && t == 0) mark_need1(ball);
    if (b < 8) {
        // was[f,h] = sum_c W1[f, h*64+c] * a_src1[h,c]; 16 rows per block.
        __shared__ float s_red[16 * 16];     // [i*16 + (0..7 ps | 8..15 pd)]
        const int h = t >> 6;
        const float as = a_src1[t];          // a_src1 is [4][64] contiguous = [t]
        const float ad = a_dst1[t];
        float wv[16];
#pragma unroll
        for (int i = 0; i < 16; i++)         // 16 independent loads, one latency
            wv[i] = W1[(b * 16 + i) * H1C + t];
        float ps[16], pd[16];
#pragma unroll
        for (int i = 0; i < 16; i++) { ps[i] = wv[i] * as; pd[i] = wv[i] * ad; }
#pragma unroll
        for (int o = 16; o; o >>= 1) {       // interleaved shfl chains pipeline
#pragma unroll
            for (int i = 0; i < 16; i++) {
                ps[i] += __shfl_down_sync(~0u, ps[i], o);
                pd[i] += __shfl_down_sync(~0u, pd[i], o);
            }
        }
        if (l == 0) {
#pragma unroll
            for (int i = 0; i < 16; i++) {
                s_red[i * 16 + w] = ps[i];
                s_red[i * 16 + 8 + w] = pd[i];
            }
        }
        __syncthreads();
        if (t < 64) {
            int i = t >> 2, hh = t & 3;
            g_was[(b * 16 + i) * 4 + hh] = s_red[i * 16 + 2 * hh] + s_red[i * 16 + 2 * hh + 1];
            g_wad[(b * 16 + i) * 4 + hh] = s_red[i * 16 + 8 + 2 * hh] + s_red[i * 16 + 8 + 2 * hh + 1];
        }
        (void)h;
        return;
    }
    const int nq = (E + 3) >> 2;
    const int* dcol = ei + E;
    const int S = (gridDim.x - 8) * 256;
    int q = (b - 8) * 256 + t;
    for (; q + 3 * S < nq; q += 4 * S) {
        int4 v0 = *reinterpret_cast<const int4*>(dcol + 4 * q);
        int4 v1 = *reinterpret_cast<const int4*>(dcol + 4 * (q + S));
        int4 v2 = *reinterpret_cast<const int4*>(dcol + 4 * (q + 2 * S));
        int4 v3 = *reinterpret_cast<const int4*>(dcol + 4 * (q + 3 * S));
        if (v0.x == ball) p1_hit(ei, E, N, 4 * q, 0);
        if (v0.y == ball) p1_hit(ei, E, N, 4 * q, 1);
        if (v0.z == ball) p1_hit(ei, E, N, 4 * q, 2);
        if (v0.w == ball) p1_hit(ei, E, N, 4 * q, 3);
        if (v1.x == ball) p1_hit(ei, E, N, 4 * (q + S), 0);
        if (v1.y == ball) p1_hit(ei, E, N, 4 * (q + S), 1);
        if (v1.z == ball) p1_hit(ei, E, N, 4 * (q + S), 2);
        if (v1.w == ball) p1_hit(ei, E, N, 4 * (q + S), 3);
        if (v2.x == ball) p1_hit(ei, E, N, 4 * (q + 2 * S), 0);
        if (v2.y == ball) p1_hit(ei, E, N, 4 * (q + 2 * S), 1);
        if (v2.z == ball) p1_hit(ei, E, N, 4 * (q + 2 * S), 2);
        if (v2.w == ball) p1_hit(ei, E, N, 4 * (q + 2 * S), 3);
        if (v3.x == ball) p1_hit(ei, E, N, 4 * (q + 3 * S), 0);
        if (v3.y == ball) p1_hit(ei, E, N, 4 * (q + 3 * S), 1);
        if (v3.z == ball) p1_hit(ei, E, N, 4 * (q + 3 * S), 2);
        if (v3.w == ball) p1_hit(ei, E, N, 4 * (q + 3 * S), 3);
    }
    for (; q < nq; q += S) {
        int base = q * 4;
        int d[4];
        if (base + 4 <= E) {
            int4 v = *reinterpret_cast<const int4*>(dcol + base);
            d[0] = v.x; d[1] = v.y; d[2] = v.z; d[3] = v.w;
        } else {
            for (int k = 0; k < 4; k++) d[k] = (base + k < E) ? dcol[base + k] : -1;
        }
#pragma unroll
        for (int k = 0; k < 4; k++) if (d[k] == ball) p1_hit(ei, E, N, base, k);
    }
}

__device__ __forceinline__ void p2_hit(const int* ei, int N, int base, int k, int dst) {
    if ((unsigned)dst >= (unsigned)N) return;
    if (g_need1[dst]) {
        int src = ei[base + k];
        if ((unsigned)src >= (unsigned)N) return;
        int p = atomicAdd(&g_cntB, 1);
        if (p < EB_CAP) { g_srcB[p] = src; g_dstB[p] = dst; }
    }
}

__global__ void k_pass2(const int* __restrict__ ei, int E, int N) {
    const int nq = (E + 3) >> 2;
    const int* dcol = ei + E;
    const int S = gridDim.x * 256;
    int q = blockIdx.x * 256 + threadIdx.x;
    for (; q + 3 * S < nq; q += 4 * S) {
        int4 v0 = *reinterpret_cast<const int4*>(dcol + 4 * q);
        int4 v1 = *reinterpret_cast<const int4*>(dcol + 4 * (q + S));
        int4 v2 = *reinterpret_cast<const int4*>(dcol + 4 * (q + 2 * S));
        int4 v3 = *reinterpret_cast<const int4*>(dcol + 4 * (q + 3 * S));
        p2_hit(ei, N, 4 * q, 0, v0.x);  p2_hit(ei, N, 4 * q, 1, v0.y);
        p2_hit(ei, N, 4 * q, 2, v0.z);  p2_hit(ei, N, 4 * q, 3, v0.w);
        p2_hit(ei, N, 4 * (q + S), 0, v1.x);  p2_hit(ei, N, 4 * (q + S), 1, v1.y);
        p2_hit(ei, N, 4 * (q + S), 2, v1.z);  p2_hit(ei, N, 4 * (q + S), 3, v1.w);
        p2_hit(ei, N, 4 * (q + 2 * S), 0, v2.x);  p2_hit(ei, N, 4 * (q + 2 * S), 1, v2.y);
        p2_hit(ei, N, 4 * (q + 2 * S), 2, v2.z);  p2_hit(ei, N, 4 * (q + 2 * S), 3, v2.w);
        p2_hit(ei, N, 4 * (q + 3 * S), 0, v3.x);  p2_hit(ei, N, 4 * (q + 3 * S), 1, v3.y);
        p2_hit(ei, N, 4 * (q + 3 * S), 2, v3.z);  p2_hit(ei, N, 4 * (q + 3 * S), 3, v3.w);
    }
    for (; q < nq; q += S) {
        int base = q * 4;
        int d[4];
        if (base + 4 <= E) {
            int4 v = *reinterpret_cast<const int4*>(dcol + base);
            d[0] = v.x; d[1] = v.y; d[2] = v.z; d[3] = v.w;
        } else {
            for (int k = 0; k < 4; k++) d[k] = (base + k < E) ? dcol[base + k] : -1;
        }
#pragma unroll
        for (int k = 0; k < 4; k++) p2_hit(ei, N, base, k, d[k]);
    }
}

// One block per need1 node; LAST finishing block also runs the final phase.
__global__ void k_agg1(const float* __restrict__ x, const float* __restrict__ W1,
                       const float* __restrict__ b1, const float* __restrict__ W2,
                       const float* __restrict__ a_src2, const float* __restrict__ a_dst2,
                       const float* __restrict__ b2,
                       const float* __restrict__ fc1_w, const float* __restrict__ fc1_b,
                       const float* __restrict__ fc2_w, const float* __restrict__ fc2_b,
                       float* __restrict__ out, int ball) {
    __shared__ float s_was[FIN * 4];
    __shared__ float s_wad[FIN * 4];
    __shared__ int   s_src[DEG_CAP];
    __shared__ float s_e[DEG_CAP * 4];
    __shared__ float s_xv[FIN];
    __shared__ float s_xagg[4 * FIN];
    __shared__ float s_r1[H1C];
    __shared__ float s_part[4 * C2];
    __shared__ float s_g2[C2];
    __shared__ float s_adv[4];
    __shared__ float s_inv[4];
    __shared__ int   s_cnt;
    __shared__ float s_fc1[C2 * 32];
    __shared__ int   s_idx[SRCA_CAP + 1];
    __shared__ float sw[SRCA_CAP + 1];
    __shared__ float s_o[C2];
    __shared__ float s_p2[8 * 32];
    __shared__ float s_z[32];
    __shared__ float s_red[16];
    __shared__ int   s_last;
    const int t = threadIdx.x, w = t >> 5, l = t & 31, b = blockIdx.x;
    const int n1 = min(g_cnt1, LIST_CAP);
    const int cb = min(g_cntB, EB_CAP);

    for (int i = t; i < C2 * 32; i += 256) s_fc1[i] = fc1_w[i];

    if (b < n1) {
        for (int i = t; i < FIN * 4; i += 256) { s_was[i] = g_was[i]; s_wad[i] = g_wad[i]; }
        for (int it = b; it < n1; it += AGG_GRID) {
            int v = g_list1[it];
            if (t == 0) s_cnt = 0;
            if (t < FIN) s_xv[t] = x[(size_t)v * FIN + t];
            __syncthreads();
            // gather in-edges, int4 over dstB (fewer dependent rounds)
            for (int base = t * 4; base < cb; base += 1024) {
                if (base + 4 <= cb) {
                    int4 dv = *reinterpret_cast<const int4*>(g_dstB + base);
                    if (dv.x == v) { int p = atomicAdd(&s_cnt, 1); if (p < DEG_CAP - 1) s_src[p] = g_srcB[base + 0]; }
                    if (dv.y == v) { int p = atomicAdd(&s_cnt, 1); if (p < DEG_CAP - 1) s_src[p] = g_srcB[base + 1]; }
                    if (dv.z == v) { int p = atomicAdd(&s_cnt, 1); if (p < DEG_CAP - 1) s_src[p] = g_srcB[base + 2]; }
                    if (dv.w == v) { int p = atomicAdd(&s_cnt, 1); if (p < DEG_CAP - 1) s_src[p] = g_srcB[base + 3]; }
                } else {
                    for (int j = base; j < cb; j++)
                        if (g_dstB[j] == v) { int p = atomicAdd(&s_cnt, 1); if (p < DEG_CAP - 1) s_src[p] = g_srcB[j]; }
                }
            }
            __syncthreads();
            if (t == 0) {
                int p = min(s_cnt, DEG_CAP - 1);
                s_src[p] = v;                 // appended self-loop
                s_cnt = p + 1;
            }
            if (w < 4) {                      // dst logits: x[v] . wad[:,h]
                float p = 0.f;
                for (int f = l; f < FIN; f += 32) p += s_xv[f] * s_wad[f * 4 + w];
#pragma unroll
                for (int o = 16; o; o >>= 1) p += __shfl_down_sync(~0u, p, o);
                if (l == 0) s_adv[w] = p;
            }
            __syncthreads();
            const int n = s_cnt;
            for (int j = w; j < n; j += 8) {  // src logits, warp per edge
                const float4 xv4 = reinterpret_cast<const float4*>(
                                       x + (size_t)s_src[j] * FIN)[l];
                float ph0 = 0.f, ph1 = 0.f, ph2 = 0.f, ph3 = 0.f;
                const float xs[4] = {xv4.x, xv4.y, xv4.z, xv4.w};
#pragma unroll
                for (int k = 0; k < 4; k++) {
                    int f = 4 * l + k;
                    ph0 += xs[k] * s_was[f * 4 + 0];
                    ph1 += xs[k] * s_was[f * 4 + 1];
                    ph2 += xs[k] * s_was[f * 4 + 2];
                    ph3 += xs[k] * s_was[f * 4 + 3];
                }
#pragma unroll
                for (int o = 16; o; o >>= 1) {
                    ph0 += __shfl_down_sync(~0u, ph0, o);
                    ph1 += __shfl_down_sync(~0u, ph1, o);
                    ph2 += __shfl_down_sync(~0u, ph2, o);
                    ph3 += __shfl_down_sync(~0u, ph3, o);
                }
                if (l == 0) {
                    float e0 = ph0 + s_adv[0], e1 = ph1 + s_adv[1];
                    float e2 = ph2 + s_adv[2], e3 = ph3 + s_adv[3];
                    s_e[j * 4 + 0] = (e0 > 0.f) ? e0 : 0.2f * e0;  // leaky_relu
                    s_e[j * 4 + 1] = (e1 > 0.f) ? e1 : 0.2f * e1;
                    s_e[j * 4 + 2] = (e2 > 0.f) ? e2 : 0.2f * e2;
                    s_e[j * 4 + 3] = (e3 > 0.f) ? e3 : 0.2f * e3;
                }
            }
            __syncthreads();
            if (t < 4) {                      // stable softmax per head
                float m = -1e30f;
                for (int j = 0; j < n; j++) m = fmaxf(m, s_e[j * 4 + t]);
                float s = 0.f;
                for (int j = 0; j < n; j++) {
                    float ww = expf(s_e[j * 4 + t] - m);
                    s_e[j * 4 + t] = ww; s += ww;
                }
                s_inv[t] = 1.f / (s + 1e-16f);
            }
            __syncthreads();
            if (t < FIN) {                    // xagg, 4-way unrolled gather
                float a0 = 0.f, a1 = 0.f, a2 = 0.f, a3 = 0.f;
                int j = 0;
                for (; j + 4 <= n; j += 4) {
                    float x0 = x[(size_t)s_src[j + 0] * FIN + t];
                    float x1 = x[(size_t)s_src[j + 1] * FIN + t];
                    float x2 = x[(size_t)s_src[j + 2] * FIN + t];
                    float x3 = x[(size_t)s_src[j + 3] * FIN + t];
                    a0 += s_e[(j+0)*4+0]*x0 + s_e[(j+1)*4+0]*x1 + s_e[(j+2)*4+0]*x2 + s_e[(j+3)*4+0]*x3;
                    a1 += s_e[(j+0)*4+1]*x0 + s_e[(j+1)*4+1]*x1 + s_e[(j+2)*4+1]*x2 + s_e[(j+3)*4+1]*x3;
                    a2 += s_e[(j+0)*4+2]*x0 + s_e[(j+1)*4+2]*x1 + s_e[(j+2)*4+2]*x2 + s_e[(j+3)*4+2]*x3;
                    a3 += s_e[(j+0)*4+3]*x0 + s_e[(j+1)*4+3]*x1 + s_e[(j+2)*4+3]*x2 + s_e[(j+3)*4+3]*x3;
                }
                for (; j < n; j++) {
                    float xv = x[(size_t)s_src[j] * FIN + t];
                    a0 += s_e[j*4+0]*xv; a1 += s_e[j*4+1]*xv;
                    a2 += s_e[j*4+2]*xv; a3 += s_e[j*4+3]*xv;
                }
                s_xagg[0 * FIN + t] = a0 * s_inv[0];
                s_xagg[1 * FIN + t] = a1 * s_inv[1];
                s_xagg[2 * FIN + t] = a2 * s_inv[2];
                s_xagg[3 * FIN + t] = a3 * s_inv[3];
            }
            __syncthreads();
            {                                 // @W1 -> r1 (32 loads in flight)
                const int h = t >> 6;
                float acc = 0.f;
#pragma unroll 32
                for (int f = 0; f < FIN; f++)
                    acc += s_xagg[h * FIN + f] * W1[f * H1C + t];
                s_r1[t] = fmaxf(acc + b1[t], 0.f);
            }
            __syncthreads();
            {                                 // g2 = r1 @ W2
                const int c = t & 63, q = t >> 6;
                float p = 0.f;
#pragma unroll 32
                for (int k = q * 64; k < q * 64 + 64; k++)
                    p += s_r1[k] * W2[k * C2 + c];
                s_part[q * C2 + c] = p;
            }
            __syncthreads();
            if (t < C2) {
                float g = s_part[t] + s_part[C2 + t] + s_part[2 * C2 + t] + s_part[3 * C2 + t];
                s_g2[t] = g;
                g_g2[(size_t)v * C2 + t] = g;
            }
            __syncthreads();
            if (w < 2) {                      // layer-2 logits: g2 . a_{src,dst}2
                const float* av = w ? a_dst2 : a_src2;
                float p = s_g2[l] * av[l] + s_g2[l + 32] * av[l + 32];
#pragma unroll
                for (int o = 16; o; o >>= 1) p += __shfl_down_sync(~0u, p, o);
                if (l == 0) { if (w) g_ad2[v] = p; else g_as2[v] = p; }
            }
            __syncthreads();
        }
    }

    // ---- done counter: last-finishing block runs the final phase ----
    __syncthreads();
    if (t == 0) {
        __threadfence();
        s_last = (atomicAdd(&g_done, 1) + 1 == gridDim.x) ? 1 : 0;
        if (s_last) __threadfence();
    }
    __syncthreads();
    if (!s_last) return;

    // ================= final (one block) ==================================
    const int nA = min(g_cntA, SRCA_CAP);
    const int cnt = nA + 1;
    for (int j = t; j < cnt; j += 256) s_idx[j] = (j < nA) ? g_srcA[j] : ball;
    __syncthreads();
    const float adv = g_ad2[ball];
    for (int j = t; j < cnt; j += 256) {
        float e = g_as2[s_idx[j]] + adv;
        sw[j] = (e > 0.f) ? e : 0.2f * e;
    }
    __syncthreads();
    float lm = -1e30f;
    for (int j = t; j < cnt; j += 256) lm = fmaxf(lm, sw[j]);
#pragma unroll
    for (int o = 16; o; o >>= 1) lm = fmaxf(lm, __shfl_down_sync(~0u, lm, o));
    if (l == 0) s_red[w] = lm;
    __syncthreads();
    if (t < 8) {
        float v = s_red[t];
#pragma unroll
        for (int o = 4; o; o >>= 1) v = fmaxf(v, __shfl_down_sync(0xffu, v, o));
        if (t == 0) s_red[0] = v;
    }
    __syncthreads();
    const float m = s_red[0];
    float ls = 0.f;
    for (int j = t; j < cnt; j += 256) { float ww = expf(sw[j] - m); sw[j] = ww; ls += ww; }
#pragma unroll
    for (int o = 16; o; o >>= 1) ls += __shfl_down_sync(~0u, ls, o);
    if (l == 0) s_red[8 + w] = ls;
    __syncthreads();
    if (t < 8) {
        float v = s_red[8 + t];
#pragma unroll
        for (int o = 4; o; o >>= 1) v += __shfl_down_sync(0xffu, v, o);
        if (t == 0) s_red[8] = v;
    }
    __syncthreads();
    const float sinv = 1.f / (s_red[8] + 1e-16f);
    {   // aggregate g2: 4 j-chunks x 64 cols (rows L2-hot)
        const int c = t & 63, q = t >> 6;
        float acc = 0.f;
        for (int j = q; j < cnt; j += 4)
            acc += sw[j] * g_g2[(size_t)s_idx[j] * C2 + c];
        s_part[q * C2 + c] = acc;
    }
    __syncthreads();
    if (t < C2) {
        float o = (s_part[t] + s_part[C2 + t] + s_part[2 * C2 + t] + s_part[3 * C2 + t])
                  * sinv + b2[t];
        s_o[t] = fmaxf(o, 0.f);
    }
    __syncthreads();
    {   // fc1 (weights in smem): 8 k-chunks x 32 outputs
        const int o = t & 31, q = t >> 5;
        float p = 0.f;
#pragma unroll
        for (int k = q * 8; k < q * 8 + 8; k++) p += s_o[k] * s_fc1[k * 32 + o];
        s_p2[q * 32 + o] = p;
    }
    __syncthreads();
    if (t < 32) {
        float a = fc1_b[t];
#pragma unroll
        for (int q = 0; q < 8; q++) a += s_p2[q * 32 + t];
        s_z[t] = fmaxf(a, 0.f);
    }
    __syncthreads();
    if (t < 2) {
        float a = fc2_b[t];
        for (int k = 0; k < 32; k++) a += s_z[k] * fc2_w[k * 2 + t];
        out[t] = a;
    }
    // ---- reset state for next graph replay ----
    __syncthreads();
    const int n1r = min(g_cnt1, LIST_CAP);
    for (int i = t; i < n1r; i += 256) g_need1[g_list1[i]] = 0;
    if (t == 0) { g_cntA = 0; g_cntB = 0; g_cnt1 = 0; g_done = 0; }
}

extern "C" void kernel_launch(void* const* d_in, const int* in_sizes, int n_in,
                              void* d_out, int out_size) {
    const float* x      = (const float*)d_in[0];
    const int*   ei     = (const int*)d_in[1];   // int32 (JAX x64-disabled)
    const float* W1     = (const float*)d_in[2];
    const float* a_src1 = (const float*)d_in[3];
    const float* a_dst1 = (const float*)d_in[4];
    const float* b1     = (const float*)d_in[5];
    const float* W2     = (const float*)d_in[6];
    const float* a_src2 = (const float*)d_in[7];
    const float* a_dst2 = (const float*)d_in[8];
    const float* b2     = (const float*)d_in[9];
    const float* fc1_w  = (const float*)d_in[10];
    const float* fc1_b  = (const float*)d_in[11];
    const float* fc2_w  = (const float*)d_in[12];
    const float* fc2_b  = (const float*)d_in[13];

    int N = in_sizes[0] / FIN;   // 20000
    int E = in_sizes[1] / 2;     // 640000
    int ball = N - 1;

    k_pass1<<<8 + SCAN_BLK, 256>>>(ei, E, ball, N, W1, a_src1, a_dst1);
    k_pass2<<<SCAN_BLK, 256>>>(ei, E, N);
    k_agg1 <<<AGG_GRID, 256>>>(x, W1, b1, W2, a_src2, a_dst2,
                               b2, fc1_w, fc1_b, fc2_w, fc2_b,
                               (float*)d_out, ball);
}

// round 14
// speedup vs baseline: 1.1842x; 1.0351x over previous
#include <cuda_runtime.h>

// BallPredictorGNN — sparse dependency cone + linear-GAT factorization.
// 2 kernels:
//   k_scan: blocks 0-7 prep was/wad || blocks 8+ scan1 (dst==ball)
//           -> grid barrier (304 co-resident blocks, launch_bounds(256,4))
//           -> scan2 over the SAME dst column, now L2-hot (edges into need1)
//   k_agg1: per-need1-node aggregate/project; last block runs final + reset.

#define NMAX      20480
#define FIN       128
#define H1C       256
#define C2        64
#define SRCA_CAP  1024
#define EB_CAP    65536
#define LIST_CAP  4096
#define DEG_CAP   512
#define AGG_GRID  64
#define SCAN_BLK  296          // 2 blocks/SM; +8 prep blocks => NB=304

__device__ int   g_need1[NMAX];
__device__ int   g_cntA, g_cntB, g_cnt1, g_done, g_barc;
__device__ int   g_srcA[SRCA_CAP];
__device__ int   g_srcB[EB_CAP];
__device__ int   g_dstB[EB_CAP];
__device__ int   g_list1[LIST_CAP];
__device__ float g_was[FIN * 4];         // [f*4+h]
__device__ float g_wad[FIN * 4];
__device__ float g_g2[(size_t)NMAX * C2];
__device__ float g_as2[NMAX], g_ad2[NMAX];

__device__ __forceinline__ void mark_need1(int v) {
    if (atomicExch(&g_need1[v], 1) == 0) {
        int p = atomicAdd(&g_cnt1, 1);
        if (p < LIST_CAP) g_list1[p] = v;
    }
}

__device__ __forceinline__ void p1_hit(const int* ei, int N, int idx) {
    int src = ei[idx];
    if ((unsigned)src >= (unsigned)N) return;
    int p = atomicAdd(&g_cntA, 1);
    if (p < SRCA_CAP) g_srcA[p] = src;
    mark_need1(src);
}

__device__ __forceinline__ void p2_hit(const int* ei, int N, int idx, int dst) {
    if ((unsigned)dst >= (unsigned)N) return;
    if (g_need1[dst]) {
        int src = ei[idx];
        if ((unsigned)src >= (unsigned)N) return;
        int p = atomicAdd(&g_cntB, 1);
        if (p < EB_CAP) { g_srcB[p] = src; g_dstB[p] = dst; }
    }
}

__global__ void __launch_bounds__(256, 4)
k_scan(const int* __restrict__ ei, int E, int ball, int N,
       const float* __restrict__ W1,
       const float* __restrict__ a_src1, const float* __restrict__ a_dst1) {
    const int b = blockIdx.x, t = threadIdx.x, NB = gridDim.x;
    const int w = t >> 5, l = t & 31;
    const int nq = (E + 3) >> 2;
    const int* dcol = ei + E;

    if (b == 0 && t == 0) mark_need1(ball);

    // ---------- phase 1: prep (b<8) || scan1 dst==ball (b>=8) ----------
    if (b < 8) {
        // was[f,h] = sum_c W1[f, h*64+c]*a_src1[h,c]; 16 rows, latency-flat
        __shared__ float s_red[16 * 16];
        const float as = a_src1[t];          // [4][64] contiguous
        const float ad = a_dst1[t];
        float wv[16];
#pragma unroll
        for (int i = 0; i < 16; i++)
            wv[i] = W1[(b * 16 + i) * H1C + t];
        float ps[16], pd[16];
#pragma unroll
        for (int i = 0; i < 16; i++) { ps[i] = wv[i] * as; pd[i] = wv[i] * ad; }
#pragma unroll
        for (int o = 16; o; o >>= 1)
#pragma unroll
            for (int i = 0; i < 16; i++) {
                ps[i] += __shfl_down_sync(~0u, ps[i], o);
                pd[i] += __shfl_down_sync(~0u, pd[i], o);
            }
        if (l == 0)
#pragma unroll
            for (int i = 0; i < 16; i++) {
                s_red[i * 16 + w] = ps[i];
                s_red[i * 16 + 8 + w] = pd[i];
            }
        __syncthreads();
        if (t < 64) {
            int i = t >> 2, hh = t & 3;
            g_was[(b * 16 + i) * 4 + hh] = s_red[i * 16 + 2 * hh] + s_red[i * 16 + 2 * hh + 1];
            g_wad[(b * 16 + i) * 4 + hh] = s_red[i * 16 + 8 + 2 * hh] + s_red[i * 16 + 8 + 2 * hh + 1];
        }
    } else {
        const int S = (NB - 8) * 256;
        int q = (b - 8) * 256 + t;
        for (; q + S < nq; q += 2 * S) {     // 2 independent int4 in flight
            int4 v0 = *reinterpret_cast<const int4*>(dcol + 4 * q);
            int4 v1 = *reinterpret_cast<const int4*>(dcol + 4 * (q + S));
            if (v0.x == ball) p1_hit(ei, N, 4 * q + 0);
            if (v0.y == ball) p1_hit(ei, N, 4 * q + 1);
            if (v0.z == ball) p1_hit(ei, N, 4 * q + 2);
            if (v0.w == ball) p1_hit(ei, N, 4 * q + 3);
            if (v1.x == ball) p1_hit(ei, N, 4 * (q + S) + 0);
            if (v1.y == ball) p1_hit(ei, N, 4 * (q + S) + 1);
            if (v1.z == ball) p1_hit(ei, N, 4 * (q + S) + 2);
            if (v1.w == ball) p1_hit(ei, N, 4 * (q + S) + 3);
        }
        for (; q < nq; q += S) {
            int base = q * 4;
            int d[4];
            if (base + 4 <= E) {
                int4 v = *reinterpret_cast<const int4*>(dcol + base);
                d[0] = v.x; d[1] = v.y; d[2] = v.z; d[3] = v.w;
            } else {
                for (int k = 0; k < 4; k++) d[k] = (base + k < E) ? dcol[base + k] : -1;
            }
#pragma unroll
            for (int k = 0; k < 4; k++) if (d[k] == ball) p1_hit(ei, N, base + k);
        }
    }

    // ---------- grid barrier (co-residency guaranteed) ----------
    __syncthreads();
    if (t == 0) {
        __threadfence();                     // release need1 writes
        atomicAdd(&g_barc, 1);
        while (*(volatile int*)&g_barc < NB) __nanosleep(128);
        __threadfence();                     // acquire
    }
    __syncthreads();

    // ---------- phase 2: scan2, dst column now L2-hot ----------
    {
        const int S = NB * 256;
        int q = b * 256 + t;
        for (; q + S < nq; q += 2 * S) {
            int4 v0 = *reinterpret_cast<const int4*>(dcol + 4 * q);
            int4 v1 = *reinterpret_cast<const int4*>(dcol + 4 * (q + S));
            p2_hit(ei, N, 4 * q + 0, v0.x);        p2_hit(ei, N, 4 * q + 1, v0.y);
            p2_hit(ei, N, 4 * q + 2, v0.z);        p2_hit(ei, N, 4 * q + 3, v0.w);
            p2_hit(ei, N, 4 * (q + S) + 0, v1.x);  p2_hit(ei, N, 4 * (q + S) + 1, v1.y);
            p2_hit(ei, N, 4 * (q + S) + 2, v1.z);  p2_hit(ei, N, 4 * (q + S) + 3, v1.w);
        }
        for (; q < nq; q += S) {
            int base = q * 4;
            int d[4];
            if (base + 4 <= E) {
                int4 v = *reinterpret_cast<const int4*>(dcol + base);
                d[0] = v.x; d[1] = v.y; d[2] = v.z; d[3] = v.w;
            } else {
                for (int k = 0; k < 4; k++) d[k] = (base + k < E) ? dcol[base + k] : -1;
            }
#pragma unroll
            for (int k = 0; k < 4; k++) p2_hit(ei, N, base + k, d[k]);
        }
    }
}

// One block per need1 node; LAST finishing block also runs the final phase.
__global__ void k_agg1(const float* __restrict__ x, const float* __restrict__ W1,
                       const float* __restrict__ b1, const float* __restrict__ W2,
                       const float* __restrict__ a_src2, const float* __restrict__ a_dst2,
                       const float* __restrict__ b2,
                       const float* __restrict__ fc1_w, const float* __restrict__ fc1_b,
                       const float* __restrict__ fc2_w, const float* __restrict__ fc2_b,
                       float* __restrict__ out, int ball) {
    __shared__ float s_was[FIN * 4];
    __shared__ float s_wad[FIN * 4];
    __shared__ int   s_src[DEG_CAP];
    __shared__ float s_e[DEG_CAP * 4];
    __shared__ float s_xv[FIN];
    __shared__ float s_xagg[4 * FIN];
    __shared__ float s_r1[H1C];
    __shared__ float s_part[4 * C2];
    __shared__ float s_g2[C2];
    __shared__ float s_adv[4];
    __shared__ float s_inv[4];
    __shared__ int   s_cnt;
    __shared__ float s_fc1[C2 * 32];
    __shared__ int   s_idx[SRCA_CAP + 1];
    __shared__ float sw[SRCA_CAP + 1];
    __shared__ float s_o[C2];
    __shared__ float s_p2[8 * 32];
    __shared__ float s_z[32];
    __shared__ float s_red[16];
    __shared__ int   s_last;
    const int t = threadIdx.x, w = t >> 5, l = t & 31, b = blockIdx.x;
    const int n1 = min(g_cnt1, LIST_CAP);
    const int cb = min(g_cntB, EB_CAP);

    for (int i = t; i < C2 * 32; i += 256) s_fc1[i] = fc1_w[i];

    if (b < n1) {
        for (int i = t; i < FIN * 4; i += 256) { s_was[i] = g_was[i]; s_wad[i] = g_wad[i]; }
        for (int it = b; it < n1; it += AGG_GRID) {
            int v = g_list1[it];
            if (t == 0) s_cnt = 0;
            if (t < FIN) s_xv[t] = x[(size_t)v * FIN + t];
            __syncthreads();
            for (int base = t * 4; base < cb; base += 1024) {
                if (base + 4 <= cb) {
                    int4 dv = *reinterpret_cast<const int4*>(g_dstB + base);
                    if (dv.x == v) { int p = atomicAdd(&s_cnt, 1); if (p < DEG_CAP - 1) s_src[p] = g_srcB[base + 0]; }
                    if (dv.y == v) { int p = atomicAdd(&s_cnt, 1); if (p < DEG_CAP - 1) s_src[p] = g_srcB[base + 1]; }
                    if (dv.z == v) { int p = atomicAdd(&s_cnt, 1); if (p < DEG_CAP - 1) s_src[p] = g_srcB[base + 2]; }
                    if (dv.w == v) { int p = atomicAdd(&s_cnt, 1); if (p < DEG_CAP - 1) s_src[p] = g_srcB[base + 3]; }
                } else {
                    for (int j = base; j < cb; j++)
                        if (g_dstB[j] == v) { int p = atomicAdd(&s_cnt, 1); if (p < DEG_CAP - 1) s_src[p] = g_srcB[j]; }
                }
            }
            __syncthreads();
            if (t == 0) {
                int p = min(s_cnt, DEG_CAP - 1);
                s_src[p] = v;                 // appended self-loop
                s_cnt = p + 1;
            }
            if (w < 4) {                      // dst logits
                float p = 0.f;
                for (int f = l; f < FIN; f += 32) p += s_xv[f] * s_wad[f * 4 + w];
#pragma unroll
                for (int o = 16; o; o >>= 1) p += __shfl_down_sync(~0u, p, o);
                if (l == 0) s_adv[w] = p;
            }
            __syncthreads();
            const int n = s_cnt;
            for (int j = w; j < n; j += 8) {  // src logits, warp per edge
                const float4 xv4 = reinterpret_cast<const float4*>(
                                       x + (size_t)s_src[j] * FIN)[l];
                float ph0 = 0.f, ph1 = 0.f, ph2 = 0.f, ph3 = 0.f;
                const float xs[4] = {xv4.x, xv4.y, xv4.z, xv4.w};
#pragma unroll
                for (int k = 0; k < 4; k++) {
                    int f = 4 * l + k;
                    ph0 += xs[k] * s_was[f * 4 + 0];
                    ph1 += xs[k] * s_was[f * 4 + 1];
                    ph2 += xs[k] * s_was[f * 4 + 2];
                    ph3 += xs[k] * s_was[f * 4 + 3];
                }
#pragma unroll
                for (int o = 16; o; o >>= 1) {
                    ph0 += __shfl_down_sync(~0u, ph0, o);
                    ph1 += __shfl_down_sync(~0u, ph1, o);
                    ph2 += __shfl_down_sync(~0u, ph2, o);
                    ph3 += __shfl_down_sync(~0u, ph3, o);
                }
                if (l == 0) {
                    float e0 = ph0 + s_adv[0], e1 = ph1 + s_adv[1];
                    float e2 = ph2 + s_adv[2], e3 = ph3 + s_adv[3];
                    s_e[j * 4 + 0] = (e0 > 0.f) ? e0 : 0.2f * e0;  // leaky_relu
                    s_e[j * 4 + 1] = (e1 > 0.f) ? e1 : 0.2f * e1;
                    s_e[j * 4 + 2] = (e2 > 0.f) ? e2 : 0.2f * e2;
                    s_e[j * 4 + 3] = (e3 > 0.f) ? e3 : 0.2f * e3;
                }
            }
            __syncthreads();
            if (t < 4) {                      // stable softmax per head
                float m = -1e30f;
                for (int j = 0; j < n; j++) m = fmaxf(m, s_e[j * 4 + t]);
                float s = 0.f;
                for (int j = 0; j < n; j++) {
                    float ww = expf(s_e[j * 4 + t] - m);
                    s_e[j * 4 + t] = ww; s += ww;
                }
                s_inv[t] = 1.f / (s + 1e-16f);
            }
            __syncthreads();
            if (t < FIN) {                    // xagg, 4-way unrolled gather
                float a0 = 0.f, a1 = 0.f, a2 = 0.f, a3 = 0.f;
                int j = 0;
                for (; j + 4 <= n; j += 4) {
                    float x0 = x[(size_t)s_src[j + 0] * FIN + t];
                    float x1 = x[(size_t)s_src[j + 1] * FIN + t];
                    float x2 = x[(size_t)s_src[j + 2] * FIN + t];
                    float x3 = x[(size_t)s_src[j + 3] * FIN + t];
                    a0 += s_e[(j+0)*4+0]*x0 + s_e[(j+1)*4+0]*x1 + s_e[(j+2)*4+0]*x2 + s_e[(j+3)*4+0]*x3;
                    a1 += s_e[(j+0)*4+1]*x0 + s_e[(j+1)*4+1]*x1 + s_e[(j+2)*4+1]*x2 + s_e[(j+3)*4+1]*x3;
                    a2 += s_e[(j+0)*4+2]*x0 + s_e[(j+1)*4+2]*x1 + s_e[(j+2)*4+2]*x2 + s_e[(j+3)*4+2]*x3;
                    a3 += s_e[(j+0)*4+3]*x0 + s_e[(j+1)*4+3]*x1 + s_e[(j+2)*4+3]*x2 + s_e[(j+3)*4+3]*x3;
                }
                for (; j < n; j++) {
                    float xv = x[(size_t)s_src[j] * FIN + t];
                    a0 += s_e[j*4+0]*xv; a1 += s_e[j*4+1]*xv;
                    a2 += s_e[j*4+2]*xv; a3 += s_e[j*4+3]*xv;
                }
                s_xagg[0 * FIN + t] = a0 * s_inv[0];
                s_xagg[1 * FIN + t] = a1 * s_inv[1];
                s_xagg[2 * FIN + t] = a2 * s_inv[2];
                s_xagg[3 * FIN + t] = a3 * s_inv[3];
            }
            __syncthreads();
            {                                 // @W1 -> r1
                const int h = t >> 6;
                float acc = 0.f;
#pragma unroll 32
                for (int f = 0; f < FIN; f++)
                    acc += s_xagg[h * FIN + f] * W1[f * H1C + t];
                s_r1[t] = fmaxf(acc + b1[t], 0.f);
            }
            __syncthreads();
            {                                 // g2 = r1 @ W2
                const int c = t & 63, q = t >> 6;
                float p = 0.f;
#pragma unroll 32
                for (int k = q * 64; k < q * 64 + 64; k++)
                    p += s_r1[k] * W2[k * C2 + c];
                s_part[q * C2 + c] = p;
            }
            __syncthreads();
            if (t < C2) {
                float g = s_part[t] + s_part[C2 + t] + s_part[2 * C2 + t] + s_part[3 * C2 + t];
                s_g2[t] = g;
                g_g2[(size_t)v * C2 + t] = g;
            }
            __syncthreads();
            if (w < 2) {                      // layer-2 logits
                const float* av = w ? a_dst2 : a_src2;
                float p = s_g2[l] * av[l] + s_g2[l + 32] * av[l + 32];
#pragma unroll
                for (int o = 16; o; o >>= 1) p += __shfl_down_sync(~0u, p, o);
                if (l == 0) { if (w) g_ad2[v] = p; else g_as2[v] = p; }
            }
            __syncthreads();
        }
    }

    // ---- done counter: last-finishing block runs the final phase ----
    __syncthreads();
    if (t == 0) {
        __threadfence();
        s_last = (atomicAdd(&g_done, 1) + 1 == gridDim.x) ? 1 : 0;
        if (s_last) __threadfence();
    }
    __syncthreads();
    if (!s_last) return;

    // ================= final (one block) ==================================
    const int nA = min(g_cntA, SRCA_CAP);
    const int cnt = nA + 1;
    for (int j = t; j < cnt; j += 256) s_idx[j] = (j < nA) ? g_srcA[j] : ball;
    __syncthreads();
    const float adv = g_ad2[ball];
    for (int j = t; j < cnt; j += 256) {
        float e = g_as2[s_idx[j]] + adv;
        sw[j] = (e > 0.f) ? e : 0.2f * e;
    }
    __syncthreads();
    float lm = -1e30f;
    for (int j = t; j < cnt; j += 256) lm = fmaxf(lm, sw[j]);
#pragma unroll
    for (int o = 16; o; o >>= 1) lm = fmaxf(lm, __shfl_down_sync(~0u, lm, o));
    if (l == 0) s_red[w] = lm;
    __syncthreads();
    if (t < 8) {
        float v = s_red[t];
#pragma unroll
        for (int o = 4; o; o >>= 1) v = fmaxf(v, __shfl_down_sync(0xffu, v, o));
        if (t == 0) s_red[0] = v;
    }
    __syncthreads();
    const float m = s_red[0];
    float ls = 0.f;
    for (int j = t; j < cnt; j += 256) { float ww = expf(sw[j] - m); sw[j] = ww; ls += ww; }
#pragma unroll
    for (int o = 16; o; o >>= 1) ls += __shfl_down_sync(~0u, ls, o);
    if (l == 0) s_red[8 + w] = ls;
    __syncthreads();
    if (t < 8) {
        float v = s_red[8 + t];
#pragma unroll
        for (int o = 4; o; o >>= 1) v += __shfl_down_sync(0xffu, v, o);
        if (t == 0) s_red[8] = v;
    }
    __syncthreads();
    const float sinv = 1.f / (s_red[8] + 1e-16f);
    {   // aggregate g2: 4 j-chunks x 64 cols (rows L2-hot)
        const int c = t & 63, q = t >> 6;
        float acc = 0.f;
        for (int j = q; j < cnt; j += 4)
            acc += sw[j] * g_g2[(size_t)s_idx[j] * C2 + c];
        s_part[q * C2 + c] = acc;
    }
    __syncthreads();
    if (t < C2) {
        float o = (s_part[t] + s_part[C2 + t] + s_part[2 * C2 + t] + s_part[3 * C2 + t])
                  * sinv + b2[t];
        s_o[t] = fmaxf(o, 0.f);
    }
    __syncthreads();
    {   // fc1 (weights in smem)
        const int o = t & 31, q = t >> 5;
        float p = 0.f;
#pragma unroll
        for (int k = q * 8; k < q * 8 + 8; k++) p += s_o[k] * s_fc1[k * 32 + o];
        s_p2[q * 32 + o] = p;
    }
    __syncthreads();
    if (t < 32) {
        float a = fc1_b[t];
#pragma unroll
        for (int q = 0; q < 8; q++) a += s_p2[q * 32 + t];
        s_z[t] = fmaxf(a, 0.f);
    }
    __syncthreads();
    if (t < 2) {
        float a = fc2_b[t];
        for (int k = 0; k < 32; k++) a += s_z[k] * fc2_w[k * 2 + t];
        out[t] = a;
    }
    // ---- reset state for next graph replay ----
    __syncthreads();
    const int n1r = min(g_cnt1, LIST_CAP);
    for (int i = t; i < n1r; i += 256) g_need1[g_list1[i]] = 0;
    if (t == 0) { g_cntA = 0; g_cntB = 0; g_cnt1 = 0; g_done = 0; g_barc = 0; }
}

extern "C" void kernel_launch(void* const* d_in, const int* in_sizes, int n_in,
                              void* d_out, int out_size) {
    const float* x      = (const float*)d_in[0];
    const int*   ei     = (const int*)d_in[1];   // int32 (JAX x64-disabled)
    const float* W1     = (const float*)d_in[2];
    const float* a_src1 = (const float*)d_in[3];
    const float* a_dst1 = (const float*)d_in[4];
    const float* b1     = (const float*)d_in[5];
    const float* W2     = (const float*)d_in[6];
    const float* a_src2 = (const float*)d_in[7];
    const float* a_dst2 = (const float*)d_in[8];
    const float* b2     = (const float*)d_in[9];
    const float* fc1_w  = (const float*)d_in[10];
    const float* fc1_b  = (const float*)d_in[11];
    const float* fc2_w  = (const float*)d_in[12];
    const float* fc2_b  = (const float*)d_in[13];

    int N = in_sizes[0] / FIN;   // 20000
    int E = in_sizes[1] / 2;     // 640000
    int ball = N - 1;

    k_scan<<<8 + SCAN_BLK, 256>>>(ei, E, ball, N, W1, a_src1, a_dst1);
    k_agg1<<<AGG_GRID, 256>>>(x, W1, b1, W2, a_src2, a_dst2,
                              b2, fc1_w, fc1_b, fc2_w, fc2_b,
                              (float*)d_out, ball);
}